// round 7
// baseline (speedup 1.0000x reference)
#include <cuda_runtime.h>
#include <cstdint>

// ---------------- problem constants ----------------
#define T_    4
#define NBN   65536
#define P_    63
#define D_    128
#define M_    262144
#define TBND  8388608
#define NBLK  2048               // GEMM blocks, 128 rows each

// dyn smem: xp floats [63][132] = 33264 B, then wd ull [63][128] = 64512 B
#define WD_OFF  33264
#define SM_GEMM (33264 + 64512)

// ---------------- device globals ----------------
__device__ float  g_h[(size_t)M_ * D_];            // 134 MB intermediate h
__device__ __align__(16) unsigned long long g_wd[P_ * D_];  // W^T duplicated pairs (w,w)
__device__ double g_psum[NBLK * D_];
__device__ double g_psq [NBLK * D_];
__device__ float  g_mean[D_];
__device__ float  g_rstd[D_];

// ---------------- packed fp32x2 helpers ----------------
__device__ __forceinline__ void fma2(unsigned long long& d,
                                     unsigned long long a, unsigned long long b){
    asm("fma.rn.f32x2 %0, %1, %2, %0;" : "+l"(d) : "l"(a), "l"(b));
}
__device__ __forceinline__ float2 up2(unsigned long long v){
    float2 f;
    asm("mov.b64 {%0, %1}, %2;" : "=f"(f.x), "=f"(f.y) : "l"(v));
    return f;
}
__device__ __forceinline__ unsigned long long dup2(float a){
    unsigned long long r;
    asm("mov.b64 %0, {%1, %1};" : "=l"(r) : "f"(a));
    return r;
}

// ---------------- K0: W [128][63] -> g_wd [p][d] = (w,w) ----------------
__global__ __launch_bounds__(256) void k_wt(const float* __restrict__ W){
    int i = blockIdx.x * 256 + threadIdx.x;
    if (i < P_ * D_){
        int p = i >> 7;
        int d = i & 127;
        g_wd[i] = dup2(W[d * P_ + p]);
    }
}

// ---------------- K1: exact fp32-sequential f32x2 GEMM --------------------
// 128 rows x 128 cols per block, 256 threads (16x16), thread tile 8x8.
// Inner loop per p: 2 LDS.128 (x row-pairs) + 4 LDS.128 (w dup-pairs) + 32 FFMA2.
// acc chain per output: acc = fma(x[m][p], W[d][p], acc), p = 0..62 sequential
// -- bit-identical to the round-1 chain that scored rel_err 0.0.
__global__ __launch_bounds__(256, 2) void k_gemm(const float* __restrict__ x){
    extern __shared__ __align__(16) float smf[];
    float* xpf = smf;                                  // [63][132] floats
    unsigned long long* wd = (unsigned long long*)((char*)smf + WD_OFF); // [63][128]
    const int tid = threadIdx.x;
    const int blk = blockIdx.x;

    // wd copy: 64512 B, L2-resident after first wave
    {
        uint4* dst = (uint4*)wd;
        const uint4* src = (const uint4*)g_wd;
        #pragma unroll
        for (int i = tid; i < 4032; i += 256) dst[i] = src[i];
    }
    // x tile transpose: xpf[p*132 + r]; row-pairs (2k,2k+1) are contiguous
    {
        const float* xg = x + (size_t)blk * (128 * P_);
        #pragma unroll
        for (int i = tid; i < 128 * P_; i += 256){
            int r = i / P_;
            int p = i - r * P_;
            xpf[p * 132 + r] = xg[i];
        }
    }
    __syncthreads();

    const int tx = tid & 15;         // cols tx*8 .. +7
    const int ty = tid >> 4;         // rows ty*8 .. +7 (4 row-pairs)

    unsigned long long acc[4][8];    // [row-pair][col]; lane.lo = even row
    #pragma unroll
    for (int rp = 0; rp < 4; rp++)
        #pragma unroll
        for (int c = 0; c < 8; c++) acc[rp][c] = 0ull;

    const unsigned long long* xrow = (const unsigned long long*)(xpf) + ty * 4;
    const unsigned long long* wrow = wd + tx * 8;

    #pragma unroll 3
    for (int p = 0; p < P_; p++){
        ulonglong2 xa = *(const ulonglong2*)(xrow + p * 66);       // rows +0,+1,+2,+3
        ulonglong2 xb = *(const ulonglong2*)(xrow + p * 66 + 2);   // rows +4..+7
        const ulonglong2* wq = (const ulonglong2*)(wrow + p * 128);
        ulonglong2 w01 = wq[0];
        ulonglong2 w23 = wq[1];
        ulonglong2 w45 = wq[2];
        ulonglong2 w67 = wq[3];
        fma2(acc[0][0], xa.x, w01.x); fma2(acc[1][0], xa.y, w01.x);
        fma2(acc[2][0], xb.x, w01.x); fma2(acc[3][0], xb.y, w01.x);
        fma2(acc[0][1], xa.x, w01.y); fma2(acc[1][1], xa.y, w01.y);
        fma2(acc[2][1], xb.x, w01.y); fma2(acc[3][1], xb.y, w01.y);
        fma2(acc[0][2], xa.x, w23.x); fma2(acc[1][2], xa.y, w23.x);
        fma2(acc[2][2], xb.x, w23.x); fma2(acc[3][2], xb.y, w23.x);
        fma2(acc[0][3], xa.x, w23.y); fma2(acc[1][3], xa.y, w23.y);
        fma2(acc[2][3], xb.x, w23.y); fma2(acc[3][3], xb.y, w23.y);
        fma2(acc[0][4], xa.x, w45.x); fma2(acc[1][4], xa.y, w45.x);
        fma2(acc[2][4], xb.x, w45.x); fma2(acc[3][4], xb.y, w45.x);
        fma2(acc[0][5], xa.x, w45.y); fma2(acc[1][5], xa.y, w45.y);
        fma2(acc[2][5], xb.x, w45.y); fma2(acc[3][5], xb.y, w45.y);
        fma2(acc[0][6], xa.x, w67.x); fma2(acc[1][6], xa.y, w67.x);
        fma2(acc[2][6], xb.x, w67.x); fma2(acc[3][6], xb.y, w67.x);
        fma2(acc[0][7], xa.x, w67.y); fma2(acc[1][7], xa.y, w67.y);
        fma2(acc[2][7], xb.x, w67.y); fma2(acc[3][7], xb.y, w67.y);
    }

    __syncthreads();    // smem reads done; reuse for stats

    // h write: per row-pair, two rows x 8 consecutive floats (2x STG.128 each)
    float* hg = g_h + (size_t)blk * (128 * 128) + tx * 8;
    #pragma unroll
    for (int rp = 0; rp < 4; rp++){
        float2 c0 = up2(acc[rp][0]), c1 = up2(acc[rp][1]);
        float2 c2 = up2(acc[rp][2]), c3 = up2(acc[rp][3]);
        float2 c4 = up2(acc[rp][4]), c5 = up2(acc[rp][5]);
        float2 c6 = up2(acc[rp][6]), c7 = up2(acc[rp][7]);
        float* r0 = hg + (ty * 8 + rp * 2) * 128;
        float* r1 = r0 + 128;
        *(float4*)(r0)     = make_float4(c0.x, c1.x, c2.x, c3.x);
        *(float4*)(r0 + 4) = make_float4(c4.x, c5.x, c6.x, c7.x);
        *(float4*)(r1)     = make_float4(c0.y, c1.y, c2.y, c3.y);
        *(float4*)(r1 + 4) = make_float4(c4.y, c5.y, c6.y, c7.y);
    }

    // stats: per-thread 8-row column sums in double, block-reduce over ty
    double* sdA = (double*)smf;              // [16][128]
    double* sdB = sdA + 16 * 128;            // [16][128]
    #pragma unroll
    for (int c = 0; c < 8; c++){
        double s = 0.0, q = 0.0;
        #pragma unroll
        for (int rp = 0; rp < 4; rp++){
            float2 f = up2(acc[rp][c]);
            s += (double)f.x + (double)f.y;
            q += (double)f.x * (double)f.x + (double)f.y * (double)f.y;
        }
        sdA[ty * 128 + tx * 8 + c] = s;
        sdB[ty * 128 + tx * 8 + c] = q;
    }
    __syncthreads();
    if (tid < 128){
        double s = 0.0, q = 0.0;
        #pragma unroll
        for (int r = 0; r < 16; r++){
            s += sdA[r * 128 + tid];
            q += sdB[r * 128 + tid];
        }
        g_psum[blk * D_ + tid] = s;
        g_psq [blk * D_ + tid] = q;
    }
}

// ---------------- K2: finalize stats (double), fold gamma/beta --------------
__global__ __launch_bounds__(256) void k_stats(const float* __restrict__ gamma,
                                               const float* __restrict__ beta){
    __shared__ double ss[256];
    __shared__ double sq[256];
    const int d = blockIdx.x;
    const int t = threadIdx.x;
    double s = 0.0, q = 0.0;
    for (int b = t; b < NBLK; b += 256){
        s += g_psum[b * D_ + d];
        q += g_psq [b * D_ + d];
    }
    ss[t] = s; sq[t] = q;
    __syncthreads();
    for (int o = 128; o > 0; o >>= 1){
        if (t < o){ ss[t] += ss[t + o]; sq[t] += sq[t + o]; }
        __syncthreads();
    }
    if (t == 0){
        double mean = ss[0] / (double)M_;
        double ex2  = sq[0] / (double)M_;
        float meanf = (float)mean;
        float varf  = (float)(ex2 - mean * mean);
        float rstd  = (float)(1.0 / sqrt((double)(varf + 1e-5f)));
        float gm = gamma[d], bt = beta[d];
        float rs = rstd * gm;
        float mn = (rs != 0.f) ? (meanf - bt / rs) : meanf;   // exact for gm=1,bt=0
        g_mean[d] = mn;
        g_rstd[d] = rs;
    }
}

// ---------------- K3: BN + 4-step LIF (proven, near DRAM roofline) ----------
__global__ __launch_bounds__(256) void k_lif(float* __restrict__ out){
    int i = blockIdx.x * 256 + threadIdx.x;
    int d0 = (i << 2) & 127;
    float4 mn = *(const float4*)(g_mean + d0);
    float4 rs = *(const float4*)(g_rstd + d0);
    size_t base = (size_t)i << 2;

    float v0 = 0.f, v1 = 0.f, v2 = 0.f, v3 = 0.f;
    #pragma unroll
    for (int t = 0; t < 4; t++){
        float4 h = *(const float4*)(g_h + base + (size_t)t * TBND);
        float n0 = (h.x - mn.x) * rs.x;
        float n1 = (h.y - mn.y) * rs.y;
        float n2 = (h.z - mn.z) * rs.z;
        float n3 = (h.w - mn.w) * rs.w;
        v0 = v0 + (n0 - v0) * 0.5f;
        v1 = v1 + (n1 - v1) * 0.5f;
        v2 = v2 + (n2 - v2) * 0.5f;
        v3 = v3 + (n3 - v3) * 0.5f;
        float4 o;
        o.x = (v0 >= 1.0f) ? 1.0f : 0.0f;
        o.y = (v1 >= 1.0f) ? 1.0f : 0.0f;
        o.z = (v2 >= 1.0f) ? 1.0f : 0.0f;
        o.w = (v3 >= 1.0f) ? 1.0f : 0.0f;
        if (v0 >= 1.0f) v0 = 0.f;
        if (v1 >= 1.0f) v1 = 0.f;
        if (v2 >= 1.0f) v2 = 0.f;
        if (v3 >= 1.0f) v3 = 0.f;
        *(float4*)(out + base + (size_t)t * TBND) = o;
    }
}

// ---------------- launch ----------------
extern "C" void kernel_launch(void* const* d_in, const int* in_sizes, int n_in,
                              void* d_out, int out_size){
    const float* x     = (const float*)d_in[0];
    const float* W     = (const float*)d_in[1];
    const float* gamma = (const float*)d_in[2];
    const float* beta  = (const float*)d_in[3];
    float* out = (float*)d_out;

    cudaFuncSetAttribute(k_gemm, cudaFuncAttributeMaxDynamicSharedMemorySize, SM_GEMM);

    k_wt   <<<32, 256>>>(W);
    k_gemm <<<NBLK, 256, SM_GEMM>>>(x);
    k_stats<<<D_, 256>>>(gamma, beta);
    k_lif  <<<TBND / 4 / 256, 256>>>(out);
}

// round 8
// speedup vs baseline: 2.4557x; 2.4557x over previous
#include <cuda_runtime.h>
#include <cuda_bf16.h>
#include <cstdint>

// ---------------- problem constants ----------------
#define T_    4
#define NBN   65536
#define P_    63
#define D_    128
#define M_    262144
#define TBND  8388608
#define NBLK  2048              // GEMM blocks (128 rows each)

// dyn smem: A limbs [0,16K,32K), B limbs [49152, 65536, 81920). Stage reuses [0,67584).
#define SM_GEMM 98304

// ---------------- device globals ----------------
__device__ float g_h[(size_t)M_ * D_];                 // 134 MB intermediate
__device__ __align__(16) unsigned char g_wb[49152];    // 3 pre-swizzled W bf16 limb tiles
__device__ float g_psum[NBLK * D_];
__device__ float g_psq [NBLK * D_];
__device__ float g_mean[D_];
__device__ float g_rstd[D_];

// ---------------- helpers ----------------
__device__ __forceinline__ uint32_t smem_u32(const void* p){
    uint32_t a;
    asm("{ .reg .u64 t; cvta.to.shared.u64 t, %1; cvt.u32.u64 %0, t; }" : "=r"(a) : "l"(p));
    return a;
}
__device__ __forceinline__ void ldsm4(uint32_t* r, uint32_t addr){
    asm volatile("ldmatrix.sync.aligned.m8n8.x4.shared.b16 {%0,%1,%2,%3}, [%4];"
        : "=r"(r[0]), "=r"(r[1]), "=r"(r[2]), "=r"(r[3]) : "r"(addr));
}
__device__ __forceinline__ void mma16816(float* c, const uint32_t* a, const uint32_t* b){
    asm volatile("mma.sync.aligned.m16n8k16.row.col.f32.bf16.bf16.f32 "
        "{%0,%1,%2,%3}, {%4,%5,%6,%7}, {%8,%9}, {%0,%1,%2,%3};"
        : "+f"(c[0]), "+f"(c[1]), "+f"(c[2]), "+f"(c[3])
        : "r"(a[0]), "r"(a[1]), "r"(a[2]), "r"(a[3]), "r"(b[0]), "r"(b[1]));
}
// swizzled byte offset inside a [128 rows x 64 bf16] tile (identical to R3)
__device__ __forceinline__ uint32_t sw_off(int row, int k){
    return (uint32_t)(row * 128 + ((((k >> 3) ^ row) & 7) << 4) + ((k & 7) << 1));
}

// ---------------- K0: W -> 3 pre-swizzled bf16 limb tiles (R3 verbatim) -----
__global__ __launch_bounds__(256) void k_wt(const float* __restrict__ W){
    int idx = blockIdx.x * 256 + threadIdx.x;     // 0..8191
    if (idx >= D_ * 64) return;
    int d = idx >> 6;
    int k = idx & 63;
    float w = (k < P_) ? W[d * P_ + k] : 0.f;
    __nv_bfloat16 w0 = __float2bfloat16(w);
    float r1 = w - __bfloat162float(w0);
    __nv_bfloat16 w1 = __float2bfloat16(r1);
    float r2 = r1 - __bfloat162float(w1);
    __nv_bfloat16 w2 = __float2bfloat16(r2);
    uint32_t off = sw_off(d, k);
    *(__nv_bfloat16*)(g_wb + off)         = w0;
    *(__nv_bfloat16*)(g_wb + 16384 + off) = w1;
    *(__nv_bfloat16*)(g_wb + 32768 + off) = w2;
}

// ---------------- K1: 6-product split-bf16 HMMA GEMM (math == R3 run) -------
__global__ __launch_bounds__(256, 2) void k_gemm(const float* __restrict__ x){
    extern __shared__ __align__(1024) unsigned char smem[];
    const uint32_t sb = smem_u32(smem);
    const int tid = threadIdx.x;
    const int w   = tid >> 5;
    const int l   = tid & 31;
    const int blk = blockIdx.x;

    // B limbs: 48KB copy of pre-swizzled tiles
    {
        uint4* bs = (uint4*)(smem + 49152);
        const uint4* gs = (const uint4*)g_wb;
        #pragma unroll
        for (int i = 0; i < 12; i++) bs[tid + i * 256] = gs[tid + i * 256];
    }
    // A limbs: 2 threads per row, packed bf16x2 3-limb split
    // (cvt.rn.bf16x2 halves are identical rounding to scalar cvt.rn.bf16 -> limb
    //  values bit-identical to R3's scalar split)
    {
        const float* xg = x + (size_t)blk * (128 * P_);
        const int row  = tid >> 1;
        const int half = tid & 1;
        const float* xr = xg + row * P_;
        #pragma unroll
        for (int i = 0; i < 16; i++){
            int p = half * 16 + i;                 // pair index 0..31
            int k = p * 2;
            float v0 = xr[k];
            float v1 = (k + 1 < P_) ? xr[k + 1] : 0.f;
            uint32_t p0;
            asm("cvt.rn.bf16x2.f32 %0, %1, %2;" : "=r"(p0) : "f"(v1), "f"(v0));
            float f0 = __uint_as_float(p0 << 16);
            float f1 = __uint_as_float(p0 & 0xffff0000u);
            float r0 = v0 - f0, r1 = v1 - f1;
            uint32_t p1;
            asm("cvt.rn.bf16x2.f32 %0, %1, %2;" : "=r"(p1) : "f"(r1), "f"(r0));
            float g0 = __uint_as_float(p1 << 16);
            float g1 = __uint_as_float(p1 & 0xffff0000u);
            float s0 = r0 - g0, s1 = r1 - g1;
            uint32_t p2;
            asm("cvt.rn.bf16x2.f32 %0, %1, %2;" : "=r"(p2) : "f"(s1), "f"(s0));
            uint32_t off = (uint32_t)(row * 128
                         + ((((k >> 3) ^ row) & 7) << 4) + ((k & 7) << 1));
            *(uint32_t*)(smem + off)         = p0;
            *(uint32_t*)(smem + 16384 + off) = p1;
            *(uint32_t*)(smem + 32768 + off) = p2;
        }
    }
    __syncthreads();

    // warp tile: 32 rows x 64 cols. 8 warps = 4 row-groups x 2 col-groups.
    const int rowg = (w >> 1) * 32;
    const int colg = (w & 1) * 64;
    const int a_r  = l & 15;
    const int a_kb = l >> 4;
    const int b_rl = (l & 7) + ((l >> 4) & 1) * 8;
    const int b_kb = (l >> 3) & 1;

    float acc[2][8][4];
    #pragma unroll
    for (int i = 0; i < 2; i++)
        #pragma unroll
        for (int j = 0; j < 8; j++)
            #pragma unroll
            for (int e = 0; e < 4; e++) acc[i][j][e] = 0.f;

    // per-element accumulation order == R3: ks outer; within ks products
    // (0,0),(1,0),(2,0),(0,1),(1,1),(0,2)
    #pragma unroll
    for (int ks = 0; ks < 4; ks++){
        uint32_t A0[2][4], A1[2][4], A2[2][4];
        #pragma unroll
        for (int rg = 0; rg < 2; rg++){
            int row = rowg + rg * 16 + a_r;
            uint32_t addr = sb + (uint32_t)row * 128
                          + (uint32_t)((((ks * 2 + a_kb) ^ (row & 7)) & 7) << 4);
            ldsm4(A0[rg], addr);
            ldsm4(A1[rg], addr + 16384);
            ldsm4(A2[rg], addr + 32768);
        }
        uint32_t Bf[4][4];
        // ---- B limb 0: products (0,0),(1,0),(2,0) ----
        #pragma unroll
        for (int j = 0; j < 4; j++){
            int rowd = colg + j * 16 + b_rl;
            uint32_t addr = sb + 49152 + (uint32_t)rowd * 128
                          + (uint32_t)((((ks * 2 + b_kb) ^ (rowd & 7)) & 7) << 4);
            ldsm4(Bf[j], addr);
        }
        #pragma unroll
        for (int rg = 0; rg < 2; rg++)
            #pragma unroll
            for (int j = 0; j < 4; j++){
                mma16816(acc[rg][2*j],   A0[rg], &Bf[j][0]);
                mma16816(acc[rg][2*j+1], A0[rg], &Bf[j][2]);
            }
        #pragma unroll
        for (int rg = 0; rg < 2; rg++)
            #pragma unroll
            for (int j = 0; j < 4; j++){
                mma16816(acc[rg][2*j],   A1[rg], &Bf[j][0]);
                mma16816(acc[rg][2*j+1], A1[rg], &Bf[j][2]);
            }
        #pragma unroll
        for (int rg = 0; rg < 2; rg++)
            #pragma unroll
            for (int j = 0; j < 4; j++){
                mma16816(acc[rg][2*j],   A2[rg], &Bf[j][0]);
                mma16816(acc[rg][2*j+1], A2[rg], &Bf[j][2]);
            }
        // ---- B limb 1: products (0,1),(1,1) ----
        #pragma unroll
        for (int j = 0; j < 4; j++){
            int rowd = colg + j * 16 + b_rl;
            uint32_t addr = sb + 65536 + (uint32_t)rowd * 128
                          + (uint32_t)((((ks * 2 + b_kb) ^ (rowd & 7)) & 7) << 4);
            ldsm4(Bf[j], addr);
        }
        #pragma unroll
        for (int rg = 0; rg < 2; rg++)
            #pragma unroll
            for (int j = 0; j < 4; j++){
                mma16816(acc[rg][2*j],   A0[rg], &Bf[j][0]);
                mma16816(acc[rg][2*j+1], A0[rg], &Bf[j][2]);
            }
        #pragma unroll
        for (int rg = 0; rg < 2; rg++)
            #pragma unroll
            for (int j = 0; j < 4; j++){
                mma16816(acc[rg][2*j],   A1[rg], &Bf[j][0]);
                mma16816(acc[rg][2*j+1], A1[rg], &Bf[j][2]);
            }
        // ---- B limb 2: product (0,2) ----
        #pragma unroll
        for (int j = 0; j < 4; j++){
            int rowd = colg + j * 16 + b_rl;
            uint32_t addr = sb + 81920 + (uint32_t)rowd * 128
                          + (uint32_t)((((ks * 2 + b_kb) ^ (rowd & 7)) & 7) << 4);
            ldsm4(Bf[j], addr);
        }
        #pragma unroll
        for (int rg = 0; rg < 2; rg++)
            #pragma unroll
            for (int j = 0; j < 4; j++){
                mma16816(acc[rg][2*j],   A0[rg], &Bf[j][0]);
                mma16816(acc[rg][2*j+1], A0[rg], &Bf[j][2]);
            }
    }

    // ---- epilogue: stage (layout == R3), coalesced h write, stats (== R3) ----
    __syncthreads();
    float* stg = (float*)smem;                 // [128][132]
    #pragma unroll
    for (int rg = 0; rg < 2; rg++){
        int rr = rowg + rg * 16 + (l >> 2);
        #pragma unroll
        for (int jh = 0; jh < 8; jh++){
            int col = colg + jh * 8 + (l & 3) * 2;
            *(float2*)(stg + rr * 132 + col)       = make_float2(acc[rg][jh][0], acc[rg][jh][1]);
            *(float2*)(stg + (rr + 8) * 132 + col) = make_float2(acc[rg][jh][2], acc[rg][jh][3]);
        }
    }
    __syncthreads();

    float* hg = g_h + (size_t)blk * (128 * 128);
    #pragma unroll
    for (int j = 0; j < 16; j++){
        int idx = tid + j * 256;
        int row = idx >> 5;
        int c4  = idx & 31;
        float4 v = *(const float4*)(stg + row * 132 + c4 * 4);
        *(float4*)(hg + row * 128 + c4 * 4) = v;
    }
    if (tid < 128){
        float s = 0.f;
        #pragma unroll 8
        for (int r = 0; r < 128; r++) s += stg[r * 132 + tid];
        g_psum[blk * D_ + tid] = s;
    } else {
        int d = tid - 128;
        float q = 0.f;
        #pragma unroll 8
        for (int r = 0; r < 128; r++){ float v = stg[r * 132 + d]; q += v * v; }
        g_psq[blk * D_ + d] = q;
    }
}

// ---------------- K2: finalize stats (R3 verbatim) ----------------
__global__ __launch_bounds__(256) void k_stats(const float* __restrict__ gamma,
                                               const float* __restrict__ beta){
    __shared__ double ss[256];
    __shared__ double sq[256];
    const int d = blockIdx.x;
    const int t = threadIdx.x;
    double s = 0.0, q = 0.0;
    for (int b = t; b < NBLK; b += 256){
        s += (double)g_psum[b * D_ + d];
        q += (double)g_psq [b * D_ + d];
    }
    ss[t] = s; sq[t] = q;
    __syncthreads();
    for (int o = 128; o > 0; o >>= 1){
        if (t < o){ ss[t] += ss[t + o]; sq[t] += sq[t + o]; }
        __syncthreads();
    }
    if (t == 0){
        double mean = ss[0] / (double)M_;
        double ex2  = sq[0] / (double)M_;
        float meanf = (float)mean;
        float varf  = (float)(ex2 - mean * mean);
        float rstd  = (float)(1.0 / sqrt((double)(varf + 1e-5f)));
        float gm = gamma[d], bt = beta[d];
        float rs = rstd * gm;
        float mn = (rs != 0.f) ? (meanf - bt / rs) : meanf;
        g_mean[d] = mn;
        g_rstd[d] = rs;
    }
}

// ---------------- K3: BN + 4-step LIF (R3 verbatim) ----------------
__global__ __launch_bounds__(256) void k_lif(float* __restrict__ out){
    int i = blockIdx.x * 256 + threadIdx.x;
    int d0 = (i << 2) & 127;
    float4 mn = *(const float4*)(g_mean + d0);
    float4 rs = *(const float4*)(g_rstd + d0);
    size_t base = (size_t)i << 2;

    float v0 = 0.f, v1 = 0.f, v2 = 0.f, v3 = 0.f;
    #pragma unroll
    for (int t = 0; t < 4; t++){
        float4 h = *(const float4*)(g_h + base + (size_t)t * TBND);
        float n0 = (h.x - mn.x) * rs.x;
        float n1 = (h.y - mn.y) * rs.y;
        float n2 = (h.z - mn.z) * rs.z;
        float n3 = (h.w - mn.w) * rs.w;
        v0 = v0 + (n0 - v0) * 0.5f;
        v1 = v1 + (n1 - v1) * 0.5f;
        v2 = v2 + (n2 - v2) * 0.5f;
        v3 = v3 + (n3 - v3) * 0.5f;
        float4 o;
        o.x = (v0 >= 1.0f) ? 1.0f : 0.0f;
        o.y = (v1 >= 1.0f) ? 1.0f : 0.0f;
        o.z = (v2 >= 1.0f) ? 1.0f : 0.0f;
        o.w = (v3 >= 1.0f) ? 1.0f : 0.0f;
        if (v0 >= 1.0f) v0 = 0.f;
        if (v1 >= 1.0f) v1 = 0.f;
        if (v2 >= 1.0f) v2 = 0.f;
        if (v3 >= 1.0f) v3 = 0.f;
        *(float4*)(out + base + (size_t)t * TBND) = o;
    }
}

// ---------------- launch ----------------
extern "C" void kernel_launch(void* const* d_in, const int* in_sizes, int n_in,
                              void* d_out, int out_size){
    const float* x     = (const float*)d_in[0];
    const float* W     = (const float*)d_in[1];
    const float* gamma = (const float*)d_in[2];
    const float* beta  = (const float*)d_in[3];
    float* out = (float*)d_out;

    cudaFuncSetAttribute(k_gemm, cudaFuncAttributeMaxDynamicSharedMemorySize, SM_GEMM);

    k_wt   <<<32, 256>>>(W);
    k_gemm <<<NBLK, 256, SM_GEMM>>>(x);
    k_stats<<<D_, 256>>>(gamma, beta);
    k_lif  <<<TBND / 4 / 256, 256>>>(out);
}